// round 3
// baseline (speedup 1.0000x reference)
#include <cuda_runtime.h>
#include <math.h>

#define NB 32
#define NT 2048
#define CF 128
#define NQ 256
#define HA 192
#define GA 576
#define HB 32
#define GB 96

__device__ float  g_embA[3 * NQ * GA];
__device__ float4 g_wpack[48 * GA];
__device__ float  g_gia[NB * NT * GA];
__device__ float  g_ha [NB * NT * HA];
__device__ float  g_gib[NB * NT * GB];
__device__ float  g_hb [NB * NT * HB];

__device__ __forceinline__ float sigf(float x) { return 1.f / (1.f + expf(-x)); }

// K0: repack w_hh_a: g_wpack[j*GA+o] = w_hh_a[o][4j..4j+3]
__global__ void k_pack(const float* __restrict__ w) {
    int i = blockIdx.x * blockDim.x + threadIdx.x;
    if (i < 48 * GA) {
        int j = i / GA, o = i % GA;
        const float* p = w + o * HA + 4 * j;
        g_wpack[i] = make_float4(p[0], p[1], p[2], p[3]);
    }
}

// K1: embA[s][q][o] = sum_d emb[q][d] * w_ih_a[o][128 + s*256 + d]
__global__ void k_proj(const float* __restrict__ emb, const float* __restrict__ wiha) {
    __shared__ float es[32][65];
    __shared__ float ws[64][65];
    int s = blockIdx.z, q0 = blockIdx.y * 32, o0 = blockIdx.x * 64;
    int t = threadIdx.x, tx = t % 64, ty = t / 64;
    float acc[8];
#pragma unroll
    for (int m = 0; m < 8; m++) acc[m] = 0.f;
    for (int kc = 0; kc < 4; kc++) {
        int k0 = kc * 64;
        for (int i = t; i < 32 * 64; i += 256) {
            int r = i >> 6, c = i & 63;
            es[r][c] = emb[(q0 + r) * NQ + k0 + c];
        }
        for (int i = t; i < 64 * 64; i += 256) {
            int r = i >> 6, c = i & 63;
            ws[r][c] = wiha[(o0 + r) * 896 + 128 + s * 256 + k0 + c];
        }
        __syncthreads();
#pragma unroll 8
        for (int k = 0; k < 64; k++) {
            float wv = ws[tx][k];
#pragma unroll
            for (int m = 0; m < 8; m++) acc[m] = fmaf(es[ty + 4 * m][k], wv, acc[m]);
        }
        __syncthreads();
    }
#pragma unroll
    for (int m = 0; m < 8; m++)
        g_embA[(s * NQ + q0 + ty + 4 * m) * GA + o0 + tx] = acc[m];
}

// K2: gia = f @ Wf^T + lerp(embA) for p, s_prev, e_prev
__global__ void k_gia(const float* __restrict__ f, const float* __restrict__ p,
                      const float* __restrict__ sp, const float* __restrict__ ep,
                      const float* __restrict__ wiha) {
    __shared__ float fs[64][65];
    __shared__ float ws[64][65];
    __shared__ int   slo[3][64];
    __shared__ float sfr[3][64];
    int o0 = blockIdx.x * 64, bt0 = blockIdx.y * 64;
    int t = threadIdx.x, tx = t & 15, ty = t >> 4;
    if (t < 192) {
        int c = t >> 6, r = t & 63;
        const float* src = (c == 0) ? p : ((c == 1) ? sp : ep);
        float raw = src[bt0 + r] * 255.f;
        int lo = (int)floorf(raw);
        lo = max(0, min(lo, 254));
        slo[c][r] = lo;
        sfr[c][r] = raw - (float)lo;
    }
    float acc[4][4];
#pragma unroll
    for (int i = 0; i < 4; i++)
#pragma unroll
        for (int j = 0; j < 4; j++) acc[i][j] = 0.f;
    for (int kc = 0; kc < 2; kc++) {
        int k0 = kc * 64;
        for (int i = t; i < 64 * 64; i += 256) {
            int r = i >> 6, c = i & 63;
            fs[r][c] = f[(bt0 + r) * CF + k0 + c];
        }
        for (int i = t; i < 64 * 64; i += 256) {
            int r = i >> 6, c = i & 63;
            ws[r][c] = wiha[(o0 + r) * 896 + k0 + c];
        }
        __syncthreads();
#pragma unroll 4
        for (int k = 0; k < 64; k++) {
            float fv[4], wv[4];
#pragma unroll
            for (int i = 0; i < 4; i++) fv[i] = fs[4 * ty + i][k];
#pragma unroll
            for (int j = 0; j < 4; j++) wv[j] = ws[4 * tx + j][k];
#pragma unroll
            for (int i = 0; i < 4; i++)
#pragma unroll
                for (int j = 0; j < 4; j++) acc[i][j] = fmaf(fv[i], wv[j], acc[i][j]);
        }
        __syncthreads();
    }
#pragma unroll
    for (int i = 0; i < 4; i++) {
        int r = 4 * ty + i;
#pragma unroll
        for (int c = 0; c < 3; c++) {
            int   lo = slo[c][r];
            float fr = sfr[c][r];
            const float4 v0 = *(const float4*)&g_embA[(c * NQ + lo) * GA + o0 + 4 * tx];
            const float4 v1 = *(const float4*)&g_embA[(c * NQ + lo + 1) * GA + o0 + 4 * tx];
            acc[i][0] += v0.x + fr * (v1.x - v0.x);
            acc[i][1] += v0.y + fr * (v1.y - v0.y);
            acc[i][2] += v0.z + fr * (v1.z - v0.z);
            acc[i][3] += v0.w + fr * (v1.w - v0.w);
        }
        *(float4*)&g_gia[(bt0 + r) * GA + o0 + 4 * tx] =
            make_float4(acc[i][0], acc[i][1], acc[i][2], acc[i][3]);
    }
}

// K3: GRU-A scan, one CTA (576 threads) per batch element
__global__ void __launch_bounds__(GA) k_scanA() {
    __shared__ float4 h4[48];
    __shared__ float  pre[2 * HA];
    __shared__ float  ghn[HA], gin[HA];
    int b = blockIdx.x, o = threadIdx.x;
    if (o < 48) h4[o] = make_float4(0.f, 0.f, 0.f, 0.f);
    __syncthreads();
    int bT = b * NT;
    float gi_c = g_gia[bT * GA + o];
    for (int t = 0; t < NT; t++) {
        float gi_n = (t + 1 < NT) ? g_gia[(bT + t + 1) * GA + o] : 0.f;
        float s0 = 0.f, s1 = 0.f, s2 = 0.f, s3 = 0.f;
#pragma unroll
        for (int j = 0; j < 48; j++) {
            float4 w  = __ldg(&g_wpack[j * GA + o]);
            float4 hv = h4[j];
            s0 = fmaf(w.x, hv.x, s0);
            s1 = fmaf(w.y, hv.y, s1);
            s2 = fmaf(w.z, hv.z, s2);
            s3 = fmaf(w.w, hv.w, s3);
        }
        float gh = (s0 + s2) + (s1 + s3);
        if (o < 2 * HA) {
            pre[o] = gh + gi_c;
        } else {
            ghn[o - 2 * HA] = gh;
            gin[o - 2 * HA] = gi_c;
        }
        __syncthreads();
        if (o < HA) {
            float r = sigf(pre[o]);
            float z = sigf(pre[HA + o]);
            float n = tanhf(gin[o] + r * ghn[o]);
            float hold = ((float*)h4)[o];
            float hn = (1.f - z) * n + z * hold;
            ((float*)h4)[o] = hn;
            g_ha[(bT + t) * HA + o] = hn;
        }
        __syncthreads();
        gi_c = gi_n;
    }
}

// K4: gib = concat(h_a, f) @ w_ih_b^T
__global__ void __launch_bounds__(384) k_gib(const float* __restrict__ f,
                                             const float* __restrict__ wihb) {
    __shared__ float xs[64][65];
    __shared__ float ws[96][65];
    int bt0 = blockIdx.x * 64;
    int t = threadIdx.x, tx = t % 24, ty = t / 24;
    float acc[4][4];
#pragma unroll
    for (int i = 0; i < 4; i++)
#pragma unroll
        for (int j = 0; j < 4; j++) acc[i][j] = 0.f;
    for (int kc = 0; kc < 5; kc++) {
        int k0 = kc * 64;
        for (int i = t; i < 64 * 64; i += 384) {
            int r = i >> 6, c = i & 63;
            xs[r][c] = (k0 < HA) ? g_ha[(bt0 + r) * HA + k0 + c]
                                 : f[(bt0 + r) * CF + (k0 - HA) + c];
        }
        for (int i = t; i < 96 * 64; i += 384) {
            int r = i >> 6, c = i & 63;
            ws[r][c] = wihb[r * 320 + k0 + c];
        }
        __syncthreads();
#pragma unroll 4
        for (int k = 0; k < 64; k++) {
            float xv[4], wv[4];
#pragma unroll
            for (int i = 0; i < 4; i++) xv[i] = xs[4 * ty + i][k];
#pragma unroll
            for (int j = 0; j < 4; j++) wv[j] = ws[4 * tx + j][k];
#pragma unroll
            for (int i = 0; i < 4; i++)
#pragma unroll
                for (int j = 0; j < 4; j++) acc[i][j] = fmaf(xv[i], wv[j], acc[i][j]);
        }
        __syncthreads();
    }
#pragma unroll
    for (int i = 0; i < 4; i++)
        *(float4*)&g_gib[(bt0 + 4 * ty + i) * GB + 4 * tx] =
            make_float4(acc[i][0], acc[i][1], acc[i][2], acc[i][3]);
}

// K5: GRU-B scan — one warp per batch, weights in registers, shfl h-broadcast
__global__ void __launch_bounds__(128) k_scanB(const float* __restrict__ whhb) {
    int l = threadIdx.x & 31;
    int b = blockIdx.x * 4 + (threadIdx.x >> 5);
    float wr[32], wz[32], wn[32];
#pragma unroll
    for (int j = 0; j < 32; j++) {
        wr[j] = whhb[l * HB + j];
        wz[j] = whhb[(HB + l) * HB + j];
        wn[j] = whhb[(2 * HB + l) * HB + j];
    }
    float h = 0.f;
    int bT = b * NT;
    for (int t = 0; t < NT; t++) {
        float gr = 0.f, gz = 0.f, gn = 0.f;
#pragma unroll
        for (int j = 0; j < 32; j++) {
            float hj = __shfl_sync(0xffffffffu, h, j);
            gr = fmaf(wr[j], hj, gr);
            gz = fmaf(wz[j], hj, gz);
            gn = fmaf(wn[j], hj, gn);
        }
        const float* gi = &g_gib[(bT + t) * GB];
        float r = sigf(gi[l] + gr);
        float z = sigf(gi[HB + l] + gz);
        float n = tanhf(gi[2 * HB + l] + r * gn);
        h = (1.f - z) * n + z * h;
        g_hb[(bT + t) * HB + l] = h;
    }
}

// K6: out[bt][q] = tanh(fcw[2q]·h+fcb[2q])*a[2q] + tanh(fcw[2q+1]·h+fcb[2q+1])*a[2q+1]
__global__ void __launch_bounds__(256) k_fc(const float* __restrict__ fcw,
                                            const float* __restrict__ fcb,
                                            const float* __restrict__ a,
                                            float* __restrict__ out) {
    __shared__ float hs[32][33];
    int q = threadIdx.x;
    int bt0 = blockIdx.x * 32;
    for (int i = q; i < 32 * 32; i += 256) {
        int r = i >> 5, c = i & 31;
        hs[r][c] = g_hb[(bt0 + r) * HB + c];
    }
    __syncthreads();
    float w0[32], w1[32];
#pragma unroll
    for (int j = 0; j < 32; j++) {
        w0[j] = fcw[(2 * q) * HB + j];
        w1[j] = fcw[(2 * q + 1) * HB + j];
    }
    float b0 = fcb[2 * q], b1 = fcb[2 * q + 1];
    float a0 = a[2 * q],   a1 = a[2 * q + 1];
    for (int r = 0; r < 32; r++) {
        float s0 = b0, s1 = b1;
#pragma unroll
        for (int j = 0; j < 32; j++) {
            float hv = hs[r][j];
            s0 = fmaf(w0[j], hv, s0);
            s1 = fmaf(w1[j], hv, s1);
        }
        out[(bt0 + r) * NQ + q] = tanhf(s0) * a0 + tanhf(s1) * a1;
    }
}

extern "C" void kernel_launch(void* const* d_in, const int* in_sizes, int n_in,
                              void* d_out, int out_size) {
    const float* f    = (const float*)d_in[0];
    const float* p    = (const float*)d_in[1];
    const float* sp   = (const float*)d_in[2];
    const float* ep   = (const float*)d_in[3];
    const float* emb  = (const float*)d_in[4];
    const float* wiha = (const float*)d_in[5];
    const float* whha = (const float*)d_in[6];
    const float* wihb = (const float*)d_in[7];
    const float* whhb = (const float*)d_in[8];
    const float* a    = (const float*)d_in[9];
    const float* fcw  = (const float*)d_in[10];
    const float* fcb  = (const float*)d_in[11];
    float* out = (float*)d_out;

    k_pack<<<(48 * GA + 255) / 256, 256>>>(whha);
    {
        dim3 g(GA / 64, NQ / 32, 3);
        k_proj<<<g, 256>>>(emb, wiha);
    }
    {
        dim3 g(GA / 64, (NB * NT) / 64, 1);
        k_gia<<<g, 256>>>(f, p, sp, ep, wiha);
    }
    k_scanA<<<NB, GA>>>();
    k_gib<<<(NB * NT) / 64, 384>>>(f, wihb);
    k_scanB<<<NB / 4, 128>>>(whhb);
    k_fc<<<(NB * NT) / 32, 256>>>(fcw, fcb, a, out);
}

// round 4
// speedup vs baseline: 2.6029x; 2.6029x over previous
#include <cuda_runtime.h>
#include <math.h>

#define NB 32
#define NT 2048
#define CF 128
#define NQ 256
#define HA 192
#define GA 576
#define HB 32
#define GB 96
#define JC 48   // j-slice per cluster CTA (192/4)

__device__ float  g_embA[3 * NQ * GA];
__device__ float  g_gia[NB * NT * GA];
__device__ float  g_ha [NB * NT * HA];
__device__ float  g_gib[NB * NT * GB];
__device__ float  g_hb [NB * NT * HB];

__device__ __forceinline__ float sigf(float x) { return 1.f / (1.f + expf(-x)); }

__device__ __forceinline__ unsigned smem_u32(const void* p) {
    unsigned a;
    asm("{ .reg .u64 t; cvta.to.shared.u64 t, %1; cvt.u32.u64 %0, t; }" : "=r"(a) : "l"(p));
    return a;
}
__device__ __forceinline__ unsigned mapa_u32(unsigned a, unsigned rank) {
    unsigned r;
    asm("mapa.shared::cluster.u32 %0, %1, %2;" : "=r"(r) : "r"(a), "r"(rank));
    return r;
}

// K1: embA[s][q][o] = sum_d emb[q][d] * w_ih_a[o][128 + s*256 + d]
__global__ void k_proj(const float* __restrict__ emb, const float* __restrict__ wiha) {
    __shared__ float es[32][65];
    __shared__ float ws[64][65];
    int s = blockIdx.z, q0 = blockIdx.y * 32, o0 = blockIdx.x * 64;
    int t = threadIdx.x, tx = t % 64, ty = t / 64;
    float acc[8];
#pragma unroll
    for (int m = 0; m < 8; m++) acc[m] = 0.f;
    for (int kc = 0; kc < 4; kc++) {
        int k0 = kc * 64;
        for (int i = t; i < 32 * 64; i += 256) {
            int r = i >> 6, c = i & 63;
            es[r][c] = emb[(q0 + r) * NQ + k0 + c];
        }
        for (int i = t; i < 64 * 64; i += 256) {
            int r = i >> 6, c = i & 63;
            ws[r][c] = wiha[(o0 + r) * 896 + 128 + s * 256 + k0 + c];
        }
        __syncthreads();
#pragma unroll 8
        for (int k = 0; k < 64; k++) {
            float wv = ws[tx][k];
#pragma unroll
            for (int m = 0; m < 8; m++) acc[m] = fmaf(es[ty + 4 * m][k], wv, acc[m]);
        }
        __syncthreads();
    }
#pragma unroll
    for (int m = 0; m < 8; m++)
        g_embA[(s * NQ + q0 + ty + 4 * m) * GA + o0 + tx] = acc[m];
}

// K2: gia = f @ Wf^T + lerp(embA) for p, s_prev, e_prev
__global__ void k_gia(const float* __restrict__ f, const float* __restrict__ p,
                      const float* __restrict__ sp, const float* __restrict__ ep,
                      const float* __restrict__ wiha) {
    __shared__ float fs[64][65];
    __shared__ float ws[64][65];
    __shared__ int   slo[3][64];
    __shared__ float sfr[3][64];
    int o0 = blockIdx.x * 64, bt0 = blockIdx.y * 64;
    int t = threadIdx.x, tx = t & 15, ty = t >> 4;
    if (t < 192) {
        int c = t >> 6, r = t & 63;
        const float* src = (c == 0) ? p : ((c == 1) ? sp : ep);
        float raw = src[bt0 + r] * 255.f;
        int lo = (int)floorf(raw);
        lo = max(0, min(lo, 254));
        slo[c][r] = lo;
        sfr[c][r] = raw - (float)lo;
    }
    float acc[4][4];
#pragma unroll
    for (int i = 0; i < 4; i++)
#pragma unroll
        for (int j = 0; j < 4; j++) acc[i][j] = 0.f;
    for (int kc = 0; kc < 2; kc++) {
        int k0 = kc * 64;
        for (int i = t; i < 64 * 64; i += 256) {
            int r = i >> 6, c = i & 63;
            fs[r][c] = f[(bt0 + r) * CF + k0 + c];
        }
        for (int i = t; i < 64 * 64; i += 256) {
            int r = i >> 6, c = i & 63;
            ws[r][c] = wiha[(o0 + r) * 896 + k0 + c];
        }
        __syncthreads();
#pragma unroll 4
        for (int k = 0; k < 64; k++) {
            float fv[4], wv[4];
#pragma unroll
            for (int i = 0; i < 4; i++) fv[i] = fs[4 * ty + i][k];
#pragma unroll
            for (int j = 0; j < 4; j++) wv[j] = ws[4 * tx + j][k];
#pragma unroll
            for (int i = 0; i < 4; i++)
#pragma unroll
                for (int j = 0; j < 4; j++) acc[i][j] = fmaf(fv[i], wv[j], acc[i][j]);
        }
        __syncthreads();
    }
#pragma unroll
    for (int i = 0; i < 4; i++) {
        int r = 4 * ty + i;
#pragma unroll
        for (int c = 0; c < 3; c++) {
            int   lo = slo[c][r];
            float fr = sfr[c][r];
            const float4 v0 = *(const float4*)&g_embA[(c * NQ + lo) * GA + o0 + 4 * tx];
            const float4 v1 = *(const float4*)&g_embA[(c * NQ + lo + 1) * GA + o0 + 4 * tx];
            acc[i][0] += v0.x + fr * (v1.x - v0.x);
            acc[i][1] += v0.y + fr * (v1.y - v0.y);
            acc[i][2] += v0.z + fr * (v1.z - v0.z);
            acc[i][3] += v0.w + fr * (v1.w - v0.w);
        }
        *(float4*)&g_gia[(bt0 + r) * GA + o0 + 4 * tx] =
            make_float4(acc[i][0], acc[i][1], acc[i][2], acc[i][3]);
    }
}

// K3: GRU-A scan. 4-CTA cluster per batch; j-split, register-resident weights,
// DSMEM partial exchange, redundant gate computation in all 4 CTAs.
__global__ void __cluster_dims__(4, 1, 1) __launch_bounds__(GA, 1)
k_scanA(const float* __restrict__ whha) {
    __shared__ float hbuf[2][JC];        // this CTA's h j-slice, double buffered
    __shared__ float part[2][4][GA];     // [buf][src_rank][output]

    int o = threadIdx.x;
    int cid = blockIdx.x >> 2;           // batch index
    unsigned rank;
    asm("mov.u32 %0, %%cluster_ctarank;" : "=r"(rank));

    // register-resident weight slice: w_hh_a[o][rank*48 .. rank*48+48)
    float4 w[12];
    const float4* wp = (const float4*)(whha + o * HA + rank * JC);
#pragma unroll
    for (int k = 0; k < 12; k++) w[k] = wp[k];

    if (o < JC) hbuf[0][o] = 0.f;
    __syncthreads();

    // remote addresses of part[b][rank][o] in the 3 peer CTAs
    unsigned pa[2][3];
#pragma unroll
    for (int b = 0; b < 2; b++) {
        unsigned la = smem_u32(&part[b][rank][o]);
#pragma unroll
        for (int k = 0; k < 3; k++) pa[b][k] = mapa_u32(la, (rank + 1 + k) & 3);
    }

    const float* gia = g_gia + (size_t)cid * NT * GA;
    bool gate = (o < HA);
    int  my_slice = o / JC;              // which rank's h-slice this gate output lands in
    float h_old = 0.f;
    float gr_i = 0.f, gz_i = 0.f, gn_i = 0.f;
    if (gate) {
        gr_i = gia[o]; gz_i = gia[HA + o]; gn_i = gia[2 * HA + o];
    }

    for (int t = 0; t < NT; t++) {
        int b = t & 1;
        // prefetch next step's gate inputs
        float ngr = 0.f, ngz = 0.f, ngn = 0.f;
        if (gate && t + 1 < NT) {
            const float* g2 = gia + (size_t)(t + 1) * GA;
            ngr = g2[o]; ngz = g2[HA + o]; ngn = g2[2 * HA + o];
        }
        // partial gh over my j-slice (weights in registers, h broadcast from smem)
        float4 s = make_float4(0.f, 0.f, 0.f, 0.f);
        const float4* h4 = (const float4*)hbuf[b];
#pragma unroll
        for (int k = 0; k < 12; k++) {
            float4 hv = h4[k];
            s.x = fmaf(w[k].x, hv.x, s.x);
            s.y = fmaf(w[k].y, hv.y, s.y);
            s.z = fmaf(w[k].z, hv.z, s.z);
            s.w = fmaf(w[k].w, hv.w, s.w);
        }
        float ps = (s.x + s.y) + (s.z + s.w);
        part[b][rank][o] = ps;                              // local copy
#pragma unroll
        for (int k = 0; k < 3; k++)                         // broadcast to peers
            asm volatile("st.shared::cluster.f32 [%0], %1;" :: "r"(pa[b][k]), "f"(ps));

        asm volatile("barrier.cluster.arrive.aligned;" ::: "memory");
        asm volatile("barrier.cluster.wait.aligned;" ::: "memory");

        if (gate) {
            float rr = gr_i, zz = gz_i, np = 0.f;
#pragma unroll
            for (int k = 0; k < 4; k++) {
                rr += part[b][k][o];
                zz += part[b][k][HA + o];
                np += part[b][k][2 * HA + o];
            }
            float rg = sigf(rr);
            float zg = sigf(zz);
            float n  = tanhf(gn_i + rg * np);
            float hn = (1.f - zg) * n + zg * h_old;
            h_old = hn;
            if (my_slice == (int)rank) {
                hbuf[b ^ 1][o - (int)rank * JC] = hn;
                g_ha[(size_t)(cid * NT + t) * HA + o] = hn;  // each rank stores its slice
            }
        }
        __syncthreads();
        gr_i = ngr; gz_i = ngz; gn_i = ngn;
    }
}

// K4: gib = concat(h_a, f) @ w_ih_b^T
__global__ void __launch_bounds__(384) k_gib(const float* __restrict__ f,
                                             const float* __restrict__ wihb) {
    __shared__ float xs[64][65];
    __shared__ float ws[96][65];
    int bt0 = blockIdx.x * 64;
    int t = threadIdx.x, tx = t % 24, ty = t / 24;
    float acc[4][4];
#pragma unroll
    for (int i = 0; i < 4; i++)
#pragma unroll
        for (int j = 0; j < 4; j++) acc[i][j] = 0.f;
    for (int kc = 0; kc < 5; kc++) {
        int k0 = kc * 64;
        for (int i = t; i < 64 * 64; i += 384) {
            int r = i >> 6, c = i & 63;
            xs[r][c] = (k0 < HA) ? g_ha[(bt0 + r) * HA + k0 + c]
                                 : f[(bt0 + r) * CF + (k0 - HA) + c];
        }
        for (int i = t; i < 96 * 64; i += 384) {
            int r = i >> 6, c = i & 63;
            ws[r][c] = wihb[r * 320 + k0 + c];
        }
        __syncthreads();
#pragma unroll 4
        for (int k = 0; k < 64; k++) {
            float xv[4], wv[4];
#pragma unroll
            for (int i = 0; i < 4; i++) xv[i] = xs[4 * ty + i][k];
#pragma unroll
            for (int j = 0; j < 4; j++) wv[j] = ws[4 * tx + j][k];
#pragma unroll
            for (int i = 0; i < 4; i++)
#pragma unroll
                for (int j = 0; j < 4; j++) acc[i][j] = fmaf(xv[i], wv[j], acc[i][j]);
        }
        __syncthreads();
    }
#pragma unroll
    for (int i = 0; i < 4; i++)
        *(float4*)&g_gib[(bt0 + 4 * ty + i) * GB + 4 * tx] =
            make_float4(acc[i][0], acc[i][1], acc[i][2], acc[i][3]);
}

// K5: GRU-B scan — one warp per batch, weights in registers, shfl h-broadcast
__global__ void __launch_bounds__(128) k_scanB(const float* __restrict__ whhb) {
    int l = threadIdx.x & 31;
    int b = blockIdx.x * 4 + (threadIdx.x >> 5);
    float wr[32], wz[32], wn[32];
#pragma unroll
    for (int j = 0; j < 32; j++) {
        wr[j] = whhb[l * HB + j];
        wz[j] = whhb[(HB + l) * HB + j];
        wn[j] = whhb[(2 * HB + l) * HB + j];
    }
    float h = 0.f;
    int bT = b * NT;
    const float* gi = &g_gib[(size_t)bT * GB];
    float gi_r = gi[l], gi_z = gi[HB + l], gi_n = gi[2 * HB + l];
    for (int t = 0; t < NT; t++) {
        float nr = 0.f, nz = 0.f, nn = 0.f;
        if (t + 1 < NT) {
            const float* g2 = &g_gib[(size_t)(bT + t + 1) * GB];
            nr = g2[l]; nz = g2[HB + l]; nn = g2[2 * HB + l];
        }
        float gr = 0.f, gz = 0.f, gn = 0.f;
#pragma unroll
        for (int j = 0; j < 32; j++) {
            float hj = __shfl_sync(0xffffffffu, h, j);
            gr = fmaf(wr[j], hj, gr);
            gz = fmaf(wz[j], hj, gz);
            gn = fmaf(wn[j], hj, gn);
        }
        float r = sigf(gi_r + gr);
        float z = sigf(gi_z + gz);
        float n = tanhf(gi_n + r * gn);
        h = (1.f - z) * n + z * h;
        g_hb[(size_t)(bT + t) * HB + l] = h;
        gi_r = nr; gi_z = nz; gi_n = nn;
    }
}

// K6: out[bt][q] = sum over pair of tanh(fc)*a
__global__ void __launch_bounds__(256) k_fc(const float* __restrict__ fcw,
                                            const float* __restrict__ fcb,
                                            const float* __restrict__ a,
                                            float* __restrict__ out) {
    __shared__ float hs[32][33];
    int q = threadIdx.x;
    int bt0 = blockIdx.x * 32;
    for (int i = q; i < 32 * 32; i += 256) {
        int r = i >> 5, c = i & 31;
        hs[r][c] = g_hb[(bt0 + r) * HB + c];
    }
    __syncthreads();
    float w0[32], w1[32];
#pragma unroll
    for (int j = 0; j < 32; j++) {
        w0[j] = fcw[(2 * q) * HB + j];
        w1[j] = fcw[(2 * q + 1) * HB + j];
    }
    float b0 = fcb[2 * q], b1 = fcb[2 * q + 1];
    float a0 = a[2 * q],   a1 = a[2 * q + 1];
    for (int r = 0; r < 32; r++) {
        float s0 = b0, s1 = b1;
#pragma unroll
        for (int j = 0; j < 32; j++) {
            float hv = hs[r][j];
            s0 = fmaf(w0[j], hv, s0);
            s1 = fmaf(w1[j], hv, s1);
        }
        out[(bt0 + r) * NQ + q] = tanhf(s0) * a0 + tanhf(s1) * a1;
    }
}

extern "C" void kernel_launch(void* const* d_in, const int* in_sizes, int n_in,
                              void* d_out, int out_size) {
    const float* f    = (const float*)d_in[0];
    const float* p    = (const float*)d_in[1];
    const float* sp   = (const float*)d_in[2];
    const float* ep   = (const float*)d_in[3];
    const float* emb  = (const float*)d_in[4];
    const float* wiha = (const float*)d_in[5];
    const float* whha = (const float*)d_in[6];
    const float* wihb = (const float*)d_in[7];
    const float* whhb = (const float*)d_in[8];
    const float* a    = (const float*)d_in[9];
    const float* fcw  = (const float*)d_in[10];
    const float* fcb  = (const float*)d_in[11];
    float* out = (float*)d_out;

    {
        dim3 g(GA / 64, NQ / 32, 3);
        k_proj<<<g, 256>>>(emb, wiha);
    }
    {
        dim3 g(GA / 64, (NB * NT) / 64, 1);
        k_gia<<<g, 256>>>(f, p, sp, ep, wiha);
    }
    k_scanA<<<NB * 4, GA>>>(whha);
    k_gib<<<(NB * NT) / 64, 384>>>(f, wihb);
    k_scanB<<<NB / 4, 128>>>(whhb);
    k_fc<<<(NB * NT) / 32, 256>>>(fcw, fcb, a, out);
}

// round 5
// speedup vs baseline: 2.6456x; 1.0164x over previous
#include <cuda_runtime.h>
#include <math.h>

#define NB 32
#define NT 2048
#define CF 128
#define NQ 256
#define HA 192
#define GA 576
#define HB 32
#define GB 96
#define JC 48

typedef unsigned long long ull;

__device__ float  g_embA[3 * NQ * GA];
__device__ float  g_gia[NB * NT * GA];
__device__ float  g_ha [NB * NT * HA];
__device__ float  g_gib[NB * NT * GB];
__device__ float  g_hb [NB * NT * HB];

__device__ __forceinline__ float sigf(float x) { return 1.f / (1.f + __expf(-x)); }
__device__ __forceinline__ float tanh_fast(float x) {
    float t = __expf(-2.f * fabsf(x));
    return copysignf(__fdividef(1.f - t, 1.f + t), x);
}
__device__ __forceinline__ ull fma2(ull a, ull b, ull c) {
    ull d;
    asm("fma.rn.f32x2 %0, %1, %2, %3;" : "=l"(d) : "l"(a), "l"(b), "l"(c));
    return d;
}
__device__ __forceinline__ float sum2(ull a) {
    float lo, hi;
    asm("mov.b64 {%0,%1}, %2;" : "=f"(lo), "=f"(hi) : "l"(a));
    return lo + hi;
}
__device__ __forceinline__ unsigned smem_u32(const void* p) {
    unsigned a;
    asm("{ .reg .u64 t; cvta.to.shared.u64 t, %1; cvt.u32.u64 %0, t; }" : "=r"(a) : "l"(p));
    return a;
}
__device__ __forceinline__ unsigned mapa_u32(unsigned a, unsigned rank) {
    unsigned r;
    asm("mapa.shared::cluster.u32 %0, %1, %2;" : "=r"(r) : "r"(a), "r"(rank));
    return r;
}

// K1: embA[s][q][o] = sum_d emb[q][d] * w_ih_a[o][128 + s*256 + d]
__global__ void k_proj(const float* __restrict__ emb, const float* __restrict__ wiha) {
    __shared__ float es[32][65];
    __shared__ float ws[64][65];
    int s = blockIdx.z, q0 = blockIdx.y * 32, o0 = blockIdx.x * 64;
    int t = threadIdx.x, tx = t % 64, ty = t / 64;
    float acc[8];
#pragma unroll
    for (int m = 0; m < 8; m++) acc[m] = 0.f;
    for (int kc = 0; kc < 4; kc++) {
        int k0 = kc * 64;
        for (int i = t; i < 32 * 64; i += 256) {
            int r = i >> 6, c = i & 63;
            es[r][c] = emb[(q0 + r) * NQ + k0 + c];
        }
        for (int i = t; i < 64 * 64; i += 256) {
            int r = i >> 6, c = i & 63;
            ws[r][c] = wiha[(o0 + r) * 896 + 128 + s * 256 + k0 + c];
        }
        __syncthreads();
#pragma unroll 8
        for (int k = 0; k < 64; k++) {
            float wv = ws[tx][k];
#pragma unroll
            for (int m = 0; m < 8; m++) acc[m] = fmaf(es[ty + 4 * m][k], wv, acc[m]);
        }
        __syncthreads();
    }
#pragma unroll
    for (int m = 0; m < 8; m++)
        g_embA[(s * NQ + q0 + ty + 4 * m) * GA + o0 + tx] = acc[m];
}

// K2: gia = f @ Wf^T + lerp(embA) for p, s_prev, e_prev
__global__ void k_gia(const float* __restrict__ f, const float* __restrict__ p,
                      const float* __restrict__ sp, const float* __restrict__ ep,
                      const float* __restrict__ wiha) {
    __shared__ float fs[64][65];
    __shared__ float ws[64][65];
    __shared__ int   slo[3][64];
    __shared__ float sfr[3][64];
    int o0 = blockIdx.x * 64, bt0 = blockIdx.y * 64;
    int t = threadIdx.x, tx = t & 15, ty = t >> 4;
    if (t < 192) {
        int c = t >> 6, r = t & 63;
        const float* src = (c == 0) ? p : ((c == 1) ? sp : ep);
        float raw = src[bt0 + r] * 255.f;
        int lo = (int)floorf(raw);
        lo = max(0, min(lo, 254));
        slo[c][r] = lo;
        sfr[c][r] = raw - (float)lo;
    }
    float acc[4][4];
#pragma unroll
    for (int i = 0; i < 4; i++)
#pragma unroll
        for (int j = 0; j < 4; j++) acc[i][j] = 0.f;
    for (int kc = 0; kc < 2; kc++) {
        int k0 = kc * 64;
        for (int i = t; i < 64 * 64; i += 256) {
            int r = i >> 6, c = i & 63;
            fs[r][c] = f[(bt0 + r) * CF + k0 + c];
        }
        for (int i = t; i < 64 * 64; i += 256) {
            int r = i >> 6, c = i & 63;
            ws[r][c] = wiha[(o0 + r) * 896 + k0 + c];
        }
        __syncthreads();
#pragma unroll 4
        for (int k = 0; k < 64; k++) {
            float fv[4], wv[4];
#pragma unroll
            for (int i = 0; i < 4; i++) fv[i] = fs[4 * ty + i][k];
#pragma unroll
            for (int j = 0; j < 4; j++) wv[j] = ws[4 * tx + j][k];
#pragma unroll
            for (int i = 0; i < 4; i++)
#pragma unroll
                for (int j = 0; j < 4; j++) acc[i][j] = fmaf(fv[i], wv[j], acc[i][j]);
        }
        __syncthreads();
    }
#pragma unroll
    for (int i = 0; i < 4; i++) {
        int r = 4 * ty + i;
#pragma unroll
        for (int c = 0; c < 3; c++) {
            int   lo = slo[c][r];
            float fr = sfr[c][r];
            const float4 v0 = *(const float4*)&g_embA[(c * NQ + lo) * GA + o0 + 4 * tx];
            const float4 v1 = *(const float4*)&g_embA[(c * NQ + lo + 1) * GA + o0 + 4 * tx];
            acc[i][0] += v0.x + fr * (v1.x - v0.x);
            acc[i][1] += v0.y + fr * (v1.y - v0.y);
            acc[i][2] += v0.z + fr * (v1.z - v0.z);
            acc[i][3] += v0.w + fr * (v1.w - v0.w);
        }
        *(float4*)&g_gia[(bt0 + r) * GA + o0 + 4 * tx] =
            make_float4(acc[i][0], acc[i][1], acc[i][2], acc[i][3]);
    }
}

// K3: GRU-A scan. 4-CTA cluster per batch; FFMA2 partials, register weights,
// DSMEM partial exchange, redundant fast gates in all 4 CTAs.
__global__ void __cluster_dims__(4, 1, 1) __launch_bounds__(GA, 1)
k_scanA(const float* __restrict__ whha) {
    __shared__ __align__(16) float hbuf[2][JC];
    __shared__ float part[2][4][GA];

    int o = threadIdx.x;
    int cid = blockIdx.x >> 2;
    unsigned rank;
    asm("mov.u32 %0, %%cluster_ctarank;" : "=r"(rank));

    // register-resident packed weights: w_hh_a[o][rank*48 .. +48) as 24 f32x2
    ull w2[24];
    {
        const ulonglong2* wp = (const ulonglong2*)(whha + o * HA + rank * JC);
#pragma unroll
        for (int k = 0; k < 12; k++) {
            ulonglong2 v = wp[k];
            w2[2 * k] = v.x;
            w2[2 * k + 1] = v.y;
        }
    }

    if (o < JC) hbuf[0][o] = 0.f;
    __syncthreads();

    unsigned pa[2][3];
#pragma unroll
    for (int b = 0; b < 2; b++) {
        unsigned la = smem_u32(&part[b][rank][o]);
#pragma unroll
        for (int k = 0; k < 3; k++) pa[b][k] = mapa_u32(la, (rank + 1 + k) & 3);
    }

    const float* gia = g_gia + (size_t)cid * NT * GA;
    bool gate = (o < HA);
    int  my_slice = o / JC;
    float h_old = 0.f;
    float gr_i = 0.f, gz_i = 0.f, gn_i = 0.f;
    if (gate) {
        gr_i = gia[o]; gz_i = gia[HA + o]; gn_i = gia[2 * HA + o];
    }

    for (int t = 0; t < NT; t++) {
        int b = t & 1;
        float ngr = 0.f, ngz = 0.f, ngn = 0.f;
        if (gate && t + 1 < NT) {
            const float* g2 = gia + (size_t)(t + 1) * GA;
            ngr = g2[o]; ngz = g2[HA + o]; ngn = g2[2 * HA + o];
        }
        // partial over my j-slice: 24 FFMA2
        ull a0 = 0ull, a1 = 0ull, a2 = 0ull, a3 = 0ull;
        const ulonglong2* h2 = (const ulonglong2*)hbuf[b];
#pragma unroll
        for (int k = 0; k < 6; k++) {
            ulonglong2 hv0 = h2[2 * k];
            ulonglong2 hv1 = h2[2 * k + 1];
            a0 = fma2(w2[4 * k + 0], hv0.x, a0);
            a1 = fma2(w2[4 * k + 1], hv0.y, a1);
            a2 = fma2(w2[4 * k + 2], hv1.x, a2);
            a3 = fma2(w2[4 * k + 3], hv1.y, a3);
        }
        float ps = (sum2(a0) + sum2(a1)) + (sum2(a2) + sum2(a3));
        part[b][rank][o] = ps;
#pragma unroll
        for (int k = 0; k < 3; k++)
            asm volatile("st.shared::cluster.f32 [%0], %1;" :: "r"(pa[b][k]), "f"(ps));

        asm volatile("barrier.cluster.arrive.aligned;" ::: "memory");
        asm volatile("barrier.cluster.wait.aligned;" ::: "memory");

        if (gate) {
            float rr = gr_i, zz = gz_i, np = 0.f;
#pragma unroll
            for (int k = 0; k < 4; k++) {
                rr += part[b][k][o];
                zz += part[b][k][HA + o];
                np += part[b][k][2 * HA + o];
            }
            float rg = sigf(rr);
            float zg = sigf(zz);
            float n  = tanh_fast(gn_i + rg * np);
            float hn = (1.f - zg) * n + zg * h_old;
            h_old = hn;
            if (my_slice == (int)rank) {
                hbuf[b ^ 1][o - (int)rank * JC] = hn;
                g_ha[(size_t)(cid * NT + t) * HA + o] = hn;
            }
        }
        __syncthreads();
        gr_i = ngr; gz_i = ngz; gn_i = ngn;
    }
}

// K4: gib = concat(h_a, f) @ w_ih_b^T
__global__ void __launch_bounds__(384) k_gib(const float* __restrict__ f,
                                             const float* __restrict__ wihb) {
    __shared__ float xs[64][65];
    __shared__ float ws[96][65];
    int bt0 = blockIdx.x * 64;
    int t = threadIdx.x, tx = t % 24, ty = t / 24;
    float acc[4][4];
#pragma unroll
    for (int i = 0; i < 4; i++)
#pragma unroll
        for (int j = 0; j < 4; j++) acc[i][j] = 0.f;
    for (int kc = 0; kc < 5; kc++) {
        int k0 = kc * 64;
        for (int i = t; i < 64 * 64; i += 384) {
            int r = i >> 6, c = i & 63;
            xs[r][c] = (k0 < HA) ? g_ha[(bt0 + r) * HA + k0 + c]
                                 : f[(bt0 + r) * CF + (k0 - HA) + c];
        }
        for (int i = t; i < 96 * 64; i += 384) {
            int r = i >> 6, c = i & 63;
            ws[r][c] = wihb[r * 320 + k0 + c];
        }
        __syncthreads();
#pragma unroll 4
        for (int k = 0; k < 64; k++) {
            float xv[4], wv[4];
#pragma unroll
            for (int i = 0; i < 4; i++) xv[i] = xs[4 * ty + i][k];
#pragma unroll
            for (int j = 0; j < 4; j++) wv[j] = ws[4 * tx + j][k];
#pragma unroll
            for (int i = 0; i < 4; i++)
#pragma unroll
                for (int j = 0; j < 4; j++) acc[i][j] = fmaf(xv[i], wv[j], acc[i][j]);
        }
        __syncthreads();
    }
#pragma unroll
    for (int i = 0; i < 4; i++)
        *(float4*)&g_gib[(bt0 + 4 * ty + i) * GB + 4 * tx] =
            make_float4(acc[i][0], acc[i][1], acc[i][2], acc[i][3]);
}

// K5: GRU-B scan — 4 batches/CTA, one warp per batch, h in smem, FFMA2
__global__ void __launch_bounds__(128) k_scanB(const float* __restrict__ whhb) {
    __shared__ __align__(16) float hsm[4][HB];
    int l = threadIdx.x & 31, wi = threadIdx.x >> 5;
    int b = blockIdx.x * 4 + wi;
    ull wr2[16], wz2[16], wn2[16];
    {
        const ulonglong2* pr = (const ulonglong2*)(whhb + l * HB);
        const ulonglong2* pz = (const ulonglong2*)(whhb + (HB + l) * HB);
        const ulonglong2* pn = (const ulonglong2*)(whhb + (2 * HB + l) * HB);
#pragma unroll
        for (int k = 0; k < 8; k++) {
            ulonglong2 vr = pr[k], vz = pz[k], vn = pn[k];
            wr2[2 * k] = vr.x; wr2[2 * k + 1] = vr.y;
            wz2[2 * k] = vz.x; wz2[2 * k + 1] = vz.y;
            wn2[2 * k] = vn.x; wn2[2 * k + 1] = vn.y;
        }
    }
    float h = 0.f;
    hsm[wi][l] = 0.f;
    __syncwarp();
    int bT = b * NT;
    const float* gi0 = &g_gib[(size_t)bT * GB];
    float gi_r = gi0[l], gi_z = gi0[HB + l], gi_n = gi0[2 * HB + l];
    for (int t = 0; t < NT; t++) {
        float nr = 0.f, nz = 0.f, nn = 0.f;
        if (t + 1 < NT) {
            const float* g2 = &g_gib[(size_t)(bT + t + 1) * GB];
            nr = g2[l]; nz = g2[HB + l]; nn = g2[2 * HB + l];
        }
        ull ar = 0ull, az = 0ull, an = 0ull;
        const ulonglong2* h2 = (const ulonglong2*)hsm[wi];
#pragma unroll
        for (int k = 0; k < 8; k++) {
            ulonglong2 hv = h2[k];
            ar = fma2(wr2[2 * k], hv.x, ar);
            az = fma2(wz2[2 * k], hv.x, az);
            an = fma2(wn2[2 * k], hv.x, an);
            ar = fma2(wr2[2 * k + 1], hv.y, ar);
            az = fma2(wz2[2 * k + 1], hv.y, az);
            an = fma2(wn2[2 * k + 1], hv.y, an);
        }
        float r = sigf(gi_r + sum2(ar));
        float z = sigf(gi_z + sum2(az));
        float n = tanh_fast(gi_n + r * sum2(an));
        h = (1.f - z) * n + z * h;
        __syncwarp();
        hsm[wi][l] = h;
        g_hb[(size_t)(bT + t) * HB + l] = h;
        __syncwarp();
        gi_r = nr; gi_z = nz; gi_n = nn;
    }
}

// K6: out[bt][q] = tanh(fc)*a summed over pair
__global__ void __launch_bounds__(256) k_fc(const float* __restrict__ fcw,
                                            const float* __restrict__ fcb,
                                            const float* __restrict__ a,
                                            float* __restrict__ out) {
    __shared__ float hs[32][33];
    int q = threadIdx.x;
    int bt0 = blockIdx.x * 32;
    for (int i = q; i < 32 * 32; i += 256) {
        int r = i >> 5, c = i & 31;
        hs[r][c] = g_hb[(bt0 + r) * HB + c];
    }
    __syncthreads();
    float w0[32], w1[32];
#pragma unroll
    for (int j = 0; j < 32; j++) {
        w0[j] = fcw[(2 * q) * HB + j];
        w1[j] = fcw[(2 * q + 1) * HB + j];
    }
    float b0 = fcb[2 * q], b1 = fcb[2 * q + 1];
    float a0 = a[2 * q],   a1 = a[2 * q + 1];
    for (int r = 0; r < 32; r++) {
        float s0 = b0, s1 = b1;
#pragma unroll
        for (int j = 0; j < 32; j++) {
            float hv = hs[r][j];
            s0 = fmaf(w0[j], hv, s0);
            s1 = fmaf(w1[j], hv, s1);
        }
        out[(bt0 + r) * NQ + q] = tanh_fast(s0) * a0 + tanh_fast(s1) * a1;
    }
}

extern "C" void kernel_launch(void* const* d_in, const int* in_sizes, int n_in,
                              void* d_out, int out_size) {
    const float* f    = (const float*)d_in[0];
    const float* p    = (const float*)d_in[1];
    const float* sp   = (const float*)d_in[2];
    const float* ep   = (const float*)d_in[3];
    const float* emb  = (const float*)d_in[4];
    const float* wiha = (const float*)d_in[5];
    const float* whha = (const float*)d_in[6];
    const float* wihb = (const float*)d_in[7];
    const float* whhb = (const float*)d_in[8];
    const float* a    = (const float*)d_in[9];
    const float* fcw  = (const float*)d_in[10];
    const float* fcb  = (const float*)d_in[11];
    float* out = (float*)d_out;

    {
        dim3 g(GA / 64, NQ / 32, 3);
        k_proj<<<g, 256>>>(emb, wiha);
    }
    {
        dim3 g(GA / 64, (NB * NT) / 64, 1);
        k_gia<<<g, 256>>>(f, p, sp, ep, wiha);
    }
    k_scanA<<<NB * 4, GA>>>(whha);
    k_gib<<<(NB * NT) / 64, 384>>>(f, wihb);
    k_scanB<<<NB / 4, 128>>>(whhb);
    k_fc<<<(NB * NT) / 32, 256>>>(fcw, fcb, a, out);
}